// round 1
// baseline (speedup 1.0000x reference)
#include <cuda_runtime.h>
#include <cstdint>

#define HWSZ (512*512)
#define BATCH 4
typedef unsigned long long ull;

// Scratch (static __device__ per allocation rules):
// g_y12: pixel-major [p][64]  : ch 0..31 = x1, ch 32..63 = x2   (268 MB)
// g_y3 : channel-major NCHW [b][64][h][w]                        (268 MB)
__device__ __align__(16) float g_y12[(size_t)BATCH*HWSZ*64];
__device__ __align__(16) float g_y3[(size_t)BATCH*64*HWSZ];
__device__ __align__(16) float2 g_wp[64*64];  // [c][j] = (W[2j][c], W[2j+1][c]); W = rows[w1;w2;w3]
__device__ float2 g_bp[64];                   // packed bias pairs

__device__ __forceinline__ float wget(const float* w1, const float* w2, const float* w3, int o, int c){
    if (o < 32) return w1[o*64 + c];
    if (o < 64) return w2[(o-32)*64 + c];
    return w3[(o-64)*64 + c];
}

__global__ void pack_weights(const float* __restrict__ w1, const float* __restrict__ b1,
                             const float* __restrict__ w2, const float* __restrict__ b2,
                             const float* __restrict__ w3, const float* __restrict__ b3){
    int t = threadIdx.x;
    for (int idx = t; idx < 64*64; idx += blockDim.x){
        int c = idx >> 6, j = idx & 63;
        g_wp[idx] = make_float2(wget(w1, w2, w3, 2*j,   c),
                                wget(w1, w2, w3, 2*j+1, c));
    }
    if (t < 64){
        int o0 = 2*t, o1 = 2*t + 1;
        float bb0 = (o0 < 32) ? b1[o0] : (o0 < 64) ? b2[o0-32] : b3[o0-64];
        float bb1 = (o1 < 32) ? b1[o1] : (o1 < 64) ? b2[o1-32] : b3[o1-64];
        g_bp[t] = make_float2(bb0, bb1);
    }
}

// ---------------------------------------------------------------------------
// Kernel A: fused 1x1 convs. 128 outputs per pixel via packed f32x2 FMA.
// Block = 256 threads, tile = 128 consecutive pixels.
// Thread (l = lane, g = warp): 4 pixels {l, l+32, l+64, l+96} x 8 output-pairs.
// ---------------------------------------------------------------------------
__global__ void __launch_bounds__(256) conv_kernel(const float* __restrict__ x){
    __shared__ float  xs[64][128];
    __shared__ float2 wp[64*64];
    __shared__ float2 bp[64];
    int t = threadIdx.x;
    size_t p0 = (size_t)blockIdx.x * 128;
    int b   = (int)(p0 >> 18);
    int hw0 = (int)(p0 & (HWSZ-1));
    const float* xb = x + ((size_t)b * 64) * HWSZ + hw0;

    // stage x tile: 64 ch x 128 px (float4, fully coalesced)
    #pragma unroll
    for (int i = 0; i < 8; i++){
        int idx = t + 256*i;              // 0..2047 float4 slots
        int c = idx >> 5, q = idx & 31;
        float4 v = *reinterpret_cast<const float4*>(xb + (size_t)c*HWSZ + 4*q);
        *reinterpret_cast<float4*>(&xs[c][4*q]) = v;
    }
    #pragma unroll
    for (int i = 0; i < 16; i++) wp[t + 256*i] = g_wp[t + 256*i];
    if (t < 64) bp[t] = g_bp[t];
    __syncthreads();

    int l = t & 31, g = t >> 5;
    int j0 = g * 8;                       // first output-pair index for this thread
    ull acc[4][8];
    #pragma unroll
    for (int j = 0; j < 8; j++){
        ull bini = *reinterpret_cast<ull*>(&bp[j0 + j]);
        #pragma unroll
        for (int k = 0; k < 4; k++) acc[k][j] = bini;
    }

    #pragma unroll
    for (int c = 0; c < 64; c++){
        ull wv[8];
        #pragma unroll
        for (int j = 0; j < 8; j++)
            wv[j] = *reinterpret_cast<ull*>(&wp[c*64 + j0 + j]);   // uniform -> smem broadcast
        #pragma unroll
        for (int k = 0; k < 4; k++){
            float xv = xs[c][l + 32*k];
            ull xx;
            asm("mov.b64 %0, {%1, %1};" : "=l"(xx) : "f"(xv));
            #pragma unroll
            for (int j = 0; j < 8; j++)
                asm("fma.rn.f32x2 %0, %1, %2, %0;" : "+l"(acc[k][j]) : "l"(xx), "l"(wv[j]));
        }
    }

    if (g < 4){
        // outputs 0..63 -> g_y12 pixel-major
        #pragma unroll
        for (int k = 0; k < 4; k++){
            size_t p = p0 + l + 32*k;
            ull* dst = reinterpret_cast<ull*>(&g_y12[p*64 + j0*2]);
            #pragma unroll
            for (int j = 0; j < 8; j++) dst[j] = acc[k][j];
        }
    } else {
        // outputs 64..127 -> g_y3 NCHW (lanes = consecutive pixels: coalesced)
        int cb = (g - 4) * 16;
        #pragma unroll
        for (int j = 0; j < 8; j++){
            float* d0 = g_y3 + ((size_t)b*64 + cb + 2*j)*HWSZ + hw0 + l;
            #pragma unroll
            for (int k = 0; k < 4; k++){
                ull a = acc[k][j];
                d0[32*k]        = __uint_as_float((unsigned)a);
                d0[HWSZ + 32*k] = __uint_as_float((unsigned)(a >> 32));
            }
        }
    }
}

// ---------------------------------------------------------------------------
// Kernel B: local sigmoid attention. Block = 256 threads, tile = 32 px (one row).
// Phase 1: warp per pixel-quad; lanes = 32 channels; warp-reduce attn per nb.
// Phase 2: lanes = 32 pixels, warp = 8 output channels; coalesced NCHW I/O.
// ---------------------------------------------------------------------------
__device__ __forceinline__ float sigmoid_fast(float a){
    float th;
    asm("tanh.approx.f32 %0, %1;" : "=f"(th) : "f"(a * 0.5f));
    return fmaf(0.5f, th, 0.5f);
}

__global__ void __launch_bounds__(256) attn_kernel(const float* __restrict__ x,
                                                   const float* __restrict__ gamma,
                                                   float* __restrict__ out){
    __shared__ float attn_s[9][32];
    int t = threadIdx.x, lane = t & 31, wi = t >> 5;
    size_t p0 = (size_t)blockIdx.x * 32;
    int b   = (int)(p0 >> 18);
    int hw0 = (int)(p0 & (HWSZ-1));
    int h = hw0 >> 9, w0 = hw0 & 511;

    // ---- phase 1: attn[nb][pix] ----
    #pragma unroll
    for (int pp = 0; pp < 4; pp++){
        int pix = wi*4 + pp;
        size_t p = p0 + pix;
        float x2v = g_y12[p*64 + 32 + lane];
        int w = w0 + pix;
        #pragma unroll
        for (int nb = 0; nb < 9; nb++){
            int dh = nb/3 - 1, dw = nb%3 - 1;
            int nh = h + dh, nw = w + dw;
            float s = 0.f;
            if ((unsigned)nh < 512u && (unsigned)nw < 512u){
                size_t np = ((size_t)b << 18) + ((size_t)(nh << 9) + nw);
                float x1v = g_y12[np*64 + lane];
                s = sigmoid_fast(x1v * x2v);
            }
            #pragma unroll
            for (int d = 16; d >= 1; d >>= 1)
                s += __shfl_xor_sync(0xffffffffu, s, d);
            if (lane == 0) attn_s[nb][pix] = s;
        }
    }
    __syncthreads();

    // ---- phase 2: out = x + gamma * sum_nb x3_shift * attn ----
    {
        int pix = lane, cg = wi;
        int w  = w0 + pix;
        int hw = hw0 + pix;
        float acc[8];
        #pragma unroll
        for (int j = 0; j < 8; j++) acc[j] = 0.f;
        #pragma unroll
        for (int nb = 0; nb < 9; nb++){
            int dh = nb/3 - 1, dw = nb%3 - 1;
            float av = attn_s[nb][pix];          // 0 for invalid neighbors
            int nh = min(max(h + dh, 0), 511);   // clamp keeps loads in-bounds
            int nw = min(max(w + dw, 0), 511);
            const float* src = g_y3 + ((size_t)b*64 + cg*8)*HWSZ + (nh << 9) + nw;
            #pragma unroll
            for (int j = 0; j < 8; j++)
                acc[j] = fmaf(src[(size_t)j*HWSZ], av, acc[j]);
        }
        float gm = __ldg(gamma);
        const float* xin = x   + ((size_t)b*64 + cg*8)*HWSZ + hw;
        float*       o   = out + ((size_t)b*64 + cg*8)*HWSZ + hw;
        #pragma unroll
        for (int j = 0; j < 8; j++)
            o[(size_t)j*HWSZ] = xin[(size_t)j*HWSZ] + gm * acc[j];
    }
}

extern "C" void kernel_launch(void* const* d_in, const int* in_sizes, int n_in,
                              void* d_out, int out_size){
    const float* x     = (const float*)d_in[0];
    const float* w1    = (const float*)d_in[1];
    const float* b1    = (const float*)d_in[2];
    const float* w2    = (const float*)d_in[3];
    const float* b2    = (const float*)d_in[4];
    const float* w3    = (const float*)d_in[5];
    const float* b3    = (const float*)d_in[6];
    const float* gamma = (const float*)d_in[7];
    float* out = (float*)d_out;

    pack_weights<<<1, 256>>>(w1, b1, w2, b2, w3, b3);
    conv_kernel<<<(BATCH*HWSZ)/128, 256>>>(x);
    attn_kernel<<<(BATCH*HWSZ)/32, 256>>>(x, gamma, out);
}

// round 4
// speedup vs baseline: 1.0014x; 1.0014x over previous
#include <cuda_runtime.h>
#include <cstdint>

#define HWSZ (512*512)
#define BATCH 4
typedef unsigned long long ull;

// Scratch (static __device__ per allocation rules):
// g_y12: pixel-major [p][64]  : ch 0..31 = x1, ch 32..63 = x2   (268 MB)
// g_y3 : channel-major NCHW [b][64][h][w]                        (268 MB)
__device__ __align__(16) float g_y12[(size_t)BATCH*HWSZ*64];
__device__ __align__(16) float g_y3[(size_t)BATCH*64*HWSZ];
__device__ __align__(16) float2 g_wp[64*64];  // [c][j] = (W[2j][c], W[2j+1][c]); W = rows[w1;w2;w3]
__device__ float2 g_bp[64];                   // packed bias pairs

__device__ __forceinline__ float wget(const float* w1, const float* w2, const float* w3, int o, int c){
    if (o < 32) return w1[o*64 + c];
    if (o < 64) return w2[(o-32)*64 + c];
    return w3[(o-64)*64 + c];
}

__global__ void pack_weights(const float* __restrict__ w1, const float* __restrict__ b1,
                             const float* __restrict__ w2, const float* __restrict__ b2,
                             const float* __restrict__ w3, const float* __restrict__ b3){
    int t = threadIdx.x;
    for (int idx = t; idx < 64*64; idx += blockDim.x){
        int c = idx >> 6, j = idx & 63;
        g_wp[idx] = make_float2(wget(w1, w2, w3, 2*j,   c),
                                wget(w1, w2, w3, 2*j+1, c));
    }
    if (t < 64){
        int o0 = 2*t, o1 = 2*t + 1;
        float bb0 = (o0 < 32) ? b1[o0] : (o0 < 64) ? b2[o0-32] : b3[o0-64];
        float bb1 = (o1 < 32) ? b1[o1] : (o1 < 64) ? b2[o1-32] : b3[o1-64];
        g_bp[t] = make_float2(bb0, bb1);
    }
}

// ---------------------------------------------------------------------------
// Kernel A: fused 1x1 convs. 128 outputs per pixel via packed f32x2 FMA.
// Block = 256 threads, tile = 128 consecutive pixels.
// Thread (l = lane, g = warp): 4 pixels {l, l+32, l+64, l+96} x 8 output-pairs.
// ---------------------------------------------------------------------------
__global__ void __launch_bounds__(256) conv_kernel(const float* __restrict__ x){
    __shared__ float  xs[64][128];
    __shared__ float2 wp[64*64];
    __shared__ float2 bp[64];
    int t = threadIdx.x;
    size_t p0 = (size_t)blockIdx.x * 128;
    int b   = (int)(p0 >> 18);
    int hw0 = (int)(p0 & (HWSZ-1));
    const float* xb = x + ((size_t)b * 64) * HWSZ + hw0;

    // stage x tile: 64 ch x 128 px (float4, fully coalesced)
    #pragma unroll
    for (int i = 0; i < 8; i++){
        int idx = t + 256*i;              // 0..2047 float4 slots
        int c = idx >> 5, q = idx & 31;
        float4 v = *reinterpret_cast<const float4*>(xb + (size_t)c*HWSZ + 4*q);
        *reinterpret_cast<float4*>(&xs[c][4*q]) = v;
    }
    #pragma unroll
    for (int i = 0; i < 16; i++) wp[t + 256*i] = g_wp[t + 256*i];
    if (t < 64) bp[t] = g_bp[t];
    __syncthreads();

    int l = t & 31, g = t >> 5;
    int j0 = g * 8;                       // first output-pair index for this thread
    ull acc[4][8];
    #pragma unroll
    for (int j = 0; j < 8; j++){
        ull bini = *reinterpret_cast<ull*>(&bp[j0 + j]);
        #pragma unroll
        for (int k = 0; k < 4; k++) acc[k][j] = bini;
    }

    #pragma unroll
    for (int c = 0; c < 64; c++){
        ull wv[8];
        #pragma unroll
        for (int j = 0; j < 8; j++)
            wv[j] = *reinterpret_cast<ull*>(&wp[c*64 + j0 + j]);   // uniform -> smem broadcast
        #pragma unroll
        for (int k = 0; k < 4; k++){
            float xv = xs[c][l + 32*k];
            ull xx;
            asm("mov.b64 %0, {%1, %1};" : "=l"(xx) : "f"(xv));
            #pragma unroll
            for (int j = 0; j < 8; j++)
                asm("fma.rn.f32x2 %0, %1, %2, %0;" : "+l"(acc[k][j]) : "l"(xx), "l"(wv[j]));
        }
    }

    if (g < 4){
        // outputs 0..63 -> g_y12 pixel-major
        #pragma unroll
        for (int k = 0; k < 4; k++){
            size_t p = p0 + l + 32*k;
            ull* dst = reinterpret_cast<ull*>(&g_y12[p*64 + j0*2]);
            #pragma unroll
            for (int j = 0; j < 8; j++) dst[j] = acc[k][j];
        }
    } else {
        // outputs 64..127 -> g_y3 NCHW (lanes = consecutive pixels: coalesced)
        int cb = (g - 4) * 16;
        #pragma unroll
        for (int j = 0; j < 8; j++){
            float* d0 = g_y3 + ((size_t)b*64 + cb + 2*j)*HWSZ + hw0 + l;
            #pragma unroll
            for (int k = 0; k < 4; k++){
                ull a = acc[k][j];
                d0[32*k]        = __uint_as_float((unsigned)a);
                d0[HWSZ + 32*k] = __uint_as_float((unsigned)(a >> 32));
            }
        }
    }
}

// ---------------------------------------------------------------------------
// Kernel B: local sigmoid attention. Block = 256 threads, tile = 32 px (one row).
// Phase 1: warp per pixel-quad; lanes = 32 channels; warp-reduce attn per nb.
// Phase 2: lanes = 32 pixels, warp = 8 output channels; coalesced NCHW I/O.
// ---------------------------------------------------------------------------
__device__ __forceinline__ float sigmoid_fast(float a){
    float th;
    asm("tanh.approx.f32 %0, %1;" : "=f"(th) : "f"(a * 0.5f));
    return fmaf(0.5f, th, 0.5f);
}

__global__ void __launch_bounds__(256) attn_kernel(const float* __restrict__ x,
                                                   const float* __restrict__ gamma,
                                                   float* __restrict__ out){
    __shared__ float attn_s[9][32];
    int t = threadIdx.x, lane = t & 31, wi = t >> 5;
    size_t p0 = (size_t)blockIdx.x * 32;
    int b   = (int)(p0 >> 18);
    int hw0 = (int)(p0 & (HWSZ-1));
    int h = hw0 >> 9, w0 = hw0 & 511;

    // ---- phase 1: attn[nb][pix] ----
    #pragma unroll
    for (int pp = 0; pp < 4; pp++){
        int pix = wi*4 + pp;
        size_t p = p0 + pix;
        float x2v = g_y12[p*64 + 32 + lane];
        int w = w0 + pix;
        #pragma unroll
        for (int nb = 0; nb < 9; nb++){
            int dh = nb/3 - 1, dw = nb%3 - 1;
            int nh = h + dh, nw = w + dw;
            float s = 0.f;
            if ((unsigned)nh < 512u && (unsigned)nw < 512u){
                size_t np = ((size_t)b << 18) + ((size_t)(nh << 9) + nw);
                float x1v = g_y12[np*64 + lane];
                s = sigmoid_fast(x1v * x2v);
            }
            #pragma unroll
            for (int d = 16; d >= 1; d >>= 1)
                s += __shfl_xor_sync(0xffffffffu, s, d);
            if (lane == 0) attn_s[nb][pix] = s;
        }
    }
    __syncthreads();

    // ---- phase 2: out = x + gamma * sum_nb x3_shift * attn ----
    {
        int pix = lane, cg = wi;
        int w  = w0 + pix;
        int hw = hw0 + pix;
        float acc[8];
        #pragma unroll
        for (int j = 0; j < 8; j++) acc[j] = 0.f;
        #pragma unroll
        for (int nb = 0; nb < 9; nb++){
            int dh = nb/3 - 1, dw = nb%3 - 1;
            float av = attn_s[nb][pix];          // 0 for invalid neighbors
            int nh = min(max(h + dh, 0), 511);   // clamp keeps loads in-bounds
            int nw = min(max(w + dw, 0), 511);
            const float* src = g_y3 + ((size_t)b*64 + cg*8)*HWSZ + (nh << 9) + nw;
            #pragma unroll
            for (int j = 0; j < 8; j++)
                acc[j] = fmaf(src[(size_t)j*HWSZ], av, acc[j]);
        }
        float gm = __ldg(gamma);
        const float* xin = x   + ((size_t)b*64 + cg*8)*HWSZ + hw;
        float*       o   = out + ((size_t)b*64 + cg*8)*HWSZ + hw;
        #pragma unroll
        for (int j = 0; j < 8; j++)
            o[(size_t)j*HWSZ] = xin[(size_t)j*HWSZ] + gm * acc[j];
    }
}

extern "C" void kernel_launch(void* const* d_in, const int* in_sizes, int n_in,
                              void* d_out, int out_size){
    const float* x     = (const float*)d_in[0];
    const float* w1    = (const float*)d_in[1];
    const float* b1    = (const float*)d_in[2];
    const float* w2    = (const float*)d_in[3];
    const float* b2    = (const float*)d_in[4];
    const float* w3    = (const float*)d_in[5];
    const float* b3    = (const float*)d_in[6];
    const float* gamma = (const float*)d_in[7];
    float* out = (float*)d_out;

    pack_weights<<<1, 256>>>(w1, b1, w2, b2, w3, b3);
    conv_kernel<<<(BATCH*HWSZ)/128, 256>>>(x);
    attn_kernel<<<(BATCH*HWSZ)/32, 256>>>(x, gamma, out);
}

// round 5
// speedup vs baseline: 1.1645x; 1.1629x over previous
#include <cuda_runtime.h>
#include <cstdint>

#define HWSZ (512*512)
#define BATCH 4
typedef unsigned long long ull;

// g_y1 : pixel-major [p][32]  (x1)
// g_y2T: channel-major NCHW [b][32][h][w]  (x2)
// g_y3 : channel-major NCHW [b][64][h][w]  (x3)
__device__ __align__(16) float g_y1 [(size_t)BATCH*HWSZ*32];
__device__ __align__(16) float g_y2T[(size_t)BATCH*32*HWSZ];
__device__ __align__(16) float g_y3 [(size_t)BATCH*64*HWSZ];
__device__ __align__(16) float2 g_wp[64*64];
__device__ float2 g_bp[64];

__device__ __forceinline__ float wget(const float* w1, const float* w2, const float* w3, int o, int c){
    if (o < 32) return w1[o*64 + c];
    if (o < 64) return w2[(o-32)*64 + c];
    return w3[(o-64)*64 + c];
}

__global__ void pack_weights(const float* __restrict__ w1, const float* __restrict__ b1,
                             const float* __restrict__ w2, const float* __restrict__ b2,
                             const float* __restrict__ w3, const float* __restrict__ b3){
    int t = threadIdx.x;
    for (int idx = t; idx < 64*64; idx += blockDim.x){
        int c = idx >> 6, j = idx & 63;
        g_wp[idx] = make_float2(wget(w1, w2, w3, 2*j, c), wget(w1, w2, w3, 2*j+1, c));
    }
    if (t < 64){
        int o0 = 2*t, o1 = 2*t + 1;
        float bb0 = (o0 < 32) ? b1[o0] : (o0 < 64) ? b2[o0-32] : b3[o0-64];
        float bb1 = (o1 < 32) ? b1[o1] : (o1 < 64) ? b2[o1-32] : b3[o1-64];
        g_bp[t] = make_float2(bb0, bb1);
    }
}

// ---------------------------------------------------------------------------
// Kernel A: fused 1x1 convs via packed f32x2 FMA (unchanged math; new epilogue:
// g=0,1 -> x1 pixel-major; g=2,3 -> x2 channel-major; g=4..7 -> x3 channel-major)
// ---------------------------------------------------------------------------
__global__ void __launch_bounds__(256) conv_kernel(const float* __restrict__ x){
    __shared__ float  xs[64][128];
    __shared__ float2 wp[64*64];
    __shared__ float2 bp[64];
    int t = threadIdx.x;
    size_t p0 = (size_t)blockIdx.x * 128;
    int b   = (int)(p0 >> 18);
    int hw0 = (int)(p0 & (HWSZ-1));
    const float* xb = x + ((size_t)b * 64) * HWSZ + hw0;

    #pragma unroll
    for (int i = 0; i < 8; i++){
        int idx = t + 256*i;
        int c = idx >> 5, q = idx & 31;
        float4 v = *reinterpret_cast<const float4*>(xb + (size_t)c*HWSZ + 4*q);
        *reinterpret_cast<float4*>(&xs[c][4*q]) = v;
    }
    #pragma unroll
    for (int i = 0; i < 16; i++) wp[t + 256*i] = g_wp[t + 256*i];
    if (t < 64) bp[t] = g_bp[t];
    __syncthreads();

    int l = t & 31, g = t >> 5;
    int j0 = g * 8;
    ull acc[4][8];
    #pragma unroll
    for (int j = 0; j < 8; j++){
        ull bini = *reinterpret_cast<ull*>(&bp[j0 + j]);
        #pragma unroll
        for (int k = 0; k < 4; k++) acc[k][j] = bini;
    }

    #pragma unroll
    for (int c = 0; c < 64; c++){
        ull wv[8];
        #pragma unroll
        for (int j = 0; j < 8; j++)
            wv[j] = *reinterpret_cast<ull*>(&wp[c*64 + j0 + j]);
        #pragma unroll
        for (int k = 0; k < 4; k++){
            float xv = xs[c][l + 32*k];
            ull xx;
            asm("mov.b64 %0, {%1, %1};" : "=l"(xx) : "f"(xv));
            #pragma unroll
            for (int j = 0; j < 8; j++)
                asm("fma.rn.f32x2 %0, %1, %2, %0;" : "+l"(acc[k][j]) : "l"(xx), "l"(wv[j]));
        }
    }

    if (g < 2){
        // out-ch 0..31 (x1) -> pixel-major [p][32]
        #pragma unroll
        for (int k = 0; k < 4; k++){
            size_t p = p0 + l + 32*k;
            ull* dst = reinterpret_cast<ull*>(&g_y1[p*32 + j0*2]);
            #pragma unroll
            for (int j = 0; j < 8; j++) dst[j] = acc[k][j];
        }
    } else {
        // out-ch 32..63 (x2) or 64..127 (x3) -> channel-major NCHW
        float* basep; int cb;
        if (g < 4){ basep = g_y2T + ((size_t)b*32)*HWSZ; cb = (g-2)*16; }
        else      { basep = g_y3  + ((size_t)b*64)*HWSZ; cb = (g-4)*16; }
        #pragma unroll
        for (int j = 0; j < 8; j++){
            float* d0 = basep + (size_t)(cb + 2*j)*HWSZ + hw0 + l;
            #pragma unroll
            for (int k = 0; k < 4; k++){
                ull a = acc[k][j];
                d0[32*k]        = __uint_as_float((unsigned)a);
                d0[HWSZ + 32*k] = __uint_as_float((unsigned)(a >> 32));
            }
        }
    }
}

// ---------------------------------------------------------------------------
// Kernel B: tiled local attention. Tile = 8 rows x 32 cols. 256 threads,
// warp wi = row, lane = col. No cross-lane reductions.
// smem: x1sT [32ch][341] (halo 10x34, pitch 341) reused as x3s [16ch][341].
// ---------------------------------------------------------------------------
#define PITCH 341
#define HALO  340

__global__ void __launch_bounds__(256) attn_tiled(const float* __restrict__ x,
                                                  const float* __restrict__ gamma,
                                                  float* __restrict__ out){
    __shared__ float sm[32*PITCH];
    int t = threadIdx.x, lane = t & 31, wi = t >> 5;
    int b = blockIdx.z, h0 = blockIdx.y*8, w0 = blockIdx.x*32;
    size_t pb = (size_t)b << 18;

    // stage x1 halo transposed: sm[ch][hp]
    for (int hp = wi; hp < HALO; hp += 8){
        int hr = hp / 34, hc = hp - hr*34;
        int nh = min(max(h0 + hr - 1, 0), 511);
        int nw = min(max(w0 + hc - 1, 0), 511);
        sm[lane*PITCH + hp] = g_y1[(pb + (size_t)((nh<<9) + nw))*32 + lane];
    }
    __syncthreads();

    int hbase = (wi+1)*34 + lane + 1;

    // phase 1: attn for own pixel (row=wi, col=lane), all 9 nb, in registers
    float av[9];
    {
        float acct[9];
        #pragma unroll
        for (int n = 0; n < 9; n++) acct[n] = 0.f;
        const float* x2p = g_y2T + ((size_t)b*32)*HWSZ + (size_t)(((h0+wi)<<9) + w0 + lane);
        #pragma unroll 4
        for (int c = 0; c < 32; c++){
            float x2h = 0.5f * __ldg(x2p + (size_t)c*HWSZ);
            #pragma unroll
            for (int n = 0; n < 9; n++){
                const int D = (n/3 - 1)*34 + (n%3 - 1);
                float th;
                asm("tanh.approx.f32 %0, %1;" : "=f"(th) : "f"(sm[c*PITCH + hbase + D] * x2h));
                acct[n] += th;
            }
        }
        #pragma unroll
        for (int n = 0; n < 9; n++){
            int nh = h0 + wi + n/3 - 1, nw = w0 + lane + n%3 - 1;
            bool ok = ((unsigned)nh < 512u) && ((unsigned)nw < 512u);
            av[n] = ok ? fmaf(0.5f, acct[n], 16.0f) : 0.f;
        }
    }

    // phase 2: out = x + gamma * sum_nb x3_shift * attn; x3 staged in 16-ch chunks
    float gm = __ldg(gamma);
    for (int ch0 = 0; ch0 < 64; ch0 += 16){
        __syncthreads();
        for (int cc = wi; cc < 16; cc += 8){
            const float* src = g_y3 + ((size_t)(b*64 + ch0 + cc))*HWSZ;
            for (int hp = lane; hp < HALO; hp += 32){
                int hr = hp / 34, hc = hp - hr*34;
                int nh = min(max(h0 + hr - 1, 0), 511);
                int nw = min(max(w0 + hc - 1, 0), 511);
                sm[cc*PITCH + hp] = src[(nh<<9) + nw];
            }
        }
        __syncthreads();
        size_t obase = ((size_t)(b*64 + ch0))*HWSZ + (size_t)(((h0+wi)<<9) + w0 + lane);
        #pragma unroll
        for (int j = 0; j < 16; j++){
            float acc = 0.f;
            #pragma unroll
            for (int n = 0; n < 9; n++){
                const int D = (n/3 - 1)*34 + (n%3 - 1);
                acc = fmaf(sm[j*PITCH + hbase + D], av[n], acc);
            }
            size_t o = obase + (size_t)j*HWSZ;
            out[o] = x[o] + gm * acc;
        }
    }
}

extern "C" void kernel_launch(void* const* d_in, const int* in_sizes, int n_in,
                              void* d_out, int out_size){
    const float* x     = (const float*)d_in[0];
    const float* w1    = (const float*)d_in[1];
    const float* b1    = (const float*)d_in[2];
    const float* w2    = (const float*)d_in[3];
    const float* b2    = (const float*)d_in[4];
    const float* w3    = (const float*)d_in[5];
    const float* b3    = (const float*)d_in[6];
    const float* gamma = (const float*)d_in[7];
    float* out = (float*)d_out;

    pack_weights<<<1, 256>>>(w1, b1, w2, b2, w3, b3);
    conv_kernel<<<(BATCH*HWSZ)/128, 256>>>(x);
    attn_tiled<<<dim3(16, 64, BATCH), 256>>>(x, gamma, out);
}

// round 8
// speedup vs baseline: 1.3125x; 1.1271x over previous
#include <cuda_runtime.h>
#include <cuda_fp16.h>
#include <cstdint>

#define HWSZ (512*512)
#define BATCH 4
typedef unsigned long long ull;

// g_y1 : pixel-major [p][32] (x1); g_y2T/g_y3: channel-major NCHW
__device__ __align__(16) float  g_y1 [(size_t)BATCH*HWSZ*32];
__device__ __align__(16) float  g_y2T[(size_t)BATCH*32*HWSZ];
__device__ __align__(16) float  g_y3 [(size_t)BATCH*64*HWSZ];
__device__ __align__(16) __half g_wA[128*64];   // swizzled fp16 weights, 128B rows
__device__ float g_bias[128];

__device__ __host__ __forceinline__ unsigned swz(unsigned b){ return b ^ ((b >> 3) & 0x70); }

__global__ void pack_weights(const float* __restrict__ w1, const float* __restrict__ b1,
                             const float* __restrict__ w2, const float* __restrict__ b2,
                             const float* __restrict__ w3, const float* __restrict__ b3){
    int t = threadIdx.x;
    for (int idx = t; idx < 128*64; idx += blockDim.x){
        int o = idx >> 6, c = idx & 63;
        float v = (o < 32) ? w1[o*64 + c] : (o < 64) ? w2[(o-32)*64 + c] : w3[(o-64)*64 + c];
        g_wA[swz((unsigned)o*128u + (unsigned)c*2u) >> 1] = __float2half(v);
    }
    if (t < 128)
        g_bias[t] = (t < 32) ? b1[t] : (t < 64) ? b2[t-32] : b3[t-64];
}

// ---------------------------------------------------------------------------
// conv_mma: D[128 out][128 px] per CTA via mma.sync m16n8k16 (f16 in, f32 acc).
// smem: ws @0 (16KB, swizzled 128B rows), xs @16384 (16KB, same layout),
//       Tbuf (float[128][66]) overlays from 0 after mainloop.  Total 33792 B.
// Warp (wid): wm = wid&3 -> 32 out-ch; wn = wid>>2 -> 64 px.
// ---------------------------------------------------------------------------
#define XS_OFF 16384
#define CONV_SMEM 33792

#define MMA16816(D, A, B) \
    asm volatile("mma.sync.aligned.m16n8k16.row.col.f32.f16.f16.f32 " \
        "{%0,%1,%2,%3}, {%4,%5,%6,%7}, {%8,%9}, {%0,%1,%2,%3};" \
        : "+f"((D)[0]), "+f"((D)[1]), "+f"((D)[2]), "+f"((D)[3]) \
        : "r"((A)[0]), "r"((A)[1]), "r"((A)[2]), "r"((A)[3]), "r"((B)[0]), "r"((B)[1]))

__global__ void __launch_bounds__(256) conv_mma(const float* __restrict__ x){
    extern __shared__ char smem[];
    int t = threadIdx.x, lane = t & 31, wid = t >> 5;
    int g = lane >> 2, tg = lane & 3;

    int tile = blockIdx.x;
    int b = tile >> 11;                 // 2048 tiles per batch (128 px each)
    int hw0 = (tile & 2047) << 7;
    const float* xb = x + ((size_t)b * 64) * HWSZ + hw0;

    // stage weights (verbatim copy of pre-swizzled tile)
    {
        const uint4* s = reinterpret_cast<const uint4*>(g_wA);
        uint4* d = reinterpret_cast<uint4*>(smem);
        #pragma unroll
        for (int i = 0; i < 4; i++) d[t + 256*i] = s[t + 256*i];
    }
    // stage x: row = px (128B = 64 ch fp16), swizzled. 2 threads per px.
    {
        int px = t >> 1, cb = (t & 1) * 32;
        #pragma unroll
        for (int cq = 0; cq < 8; cq++){
            int c = cb + cq*4;
            __half2 h0 = __floats2half2_rn(xb[(size_t)c*HWSZ + px],     xb[(size_t)(c+1)*HWSZ + px]);
            __half2 h1 = __floats2half2_rn(xb[(size_t)(c+2)*HWSZ + px], xb[(size_t)(c+3)*HWSZ + px]);
            uint2 pkt;
            pkt.x = *reinterpret_cast<uint32_t*>(&h0);
            pkt.y = *reinterpret_cast<uint32_t*>(&h1);
            *reinterpret_cast<uint2*>(smem + XS_OFF + swz((unsigned)px*128u + (unsigned)c*2u)) = pkt;
        }
    }
    __syncthreads();

    int m0 = (wid & 3) * 32, n0 = (wid >> 2) * 64;

    // accumulators init with bias: d[mt][nt] = {D[g][2t],D[g][2t+1],D[g+8][2t],D[g+8][2t+1]}
    float d[2][8][4];
    #pragma unroll
    for (int mt = 0; mt < 2; mt++){
        float blo = g_bias[m0 + mt*16 + g];
        float bhi = g_bias[m0 + mt*16 + g + 8];
        #pragma unroll
        for (int nt = 0; nt < 8; nt++){
            d[mt][nt][0] = blo; d[mt][nt][1] = blo;
            d[mt][nt][2] = bhi; d[mt][nt][3] = bhi;
        }
    }

    const uint32_t* wsv = reinterpret_cast<const uint32_t*>(smem);
    const uint32_t* xsv = reinterpret_cast<const uint32_t*>(smem + XS_OFF);

    #pragma unroll
    for (int ks = 0; ks < 4; ks++){
        uint32_t a[2][4];
        #pragma unroll
        for (int mt = 0; mt < 2; mt++){
            unsigned r0 = (unsigned)(m0 + mt*16 + g);
            unsigned c0 = (unsigned)(ks*32 + tg*4);
            a[mt][0] = wsv[swz(r0*128u + c0) >> 2];
            a[mt][1] = wsv[swz((r0+8)*128u + c0) >> 2];
            a[mt][2] = wsv[swz(r0*128u + c0 + 16) >> 2];
            a[mt][3] = wsv[swz((r0+8)*128u + c0 + 16) >> 2];
        }
        #pragma unroll
        for (int nt = 0; nt < 8; nt++){
            unsigned pr = (unsigned)(n0 + nt*8 + g);
            unsigned bb = pr*128u + (unsigned)(ks*32 + tg*4);
            uint32_t bfrag[2];
            bfrag[0] = xsv[swz(bb) >> 2];
            bfrag[1] = xsv[swz(bb + 16) >> 2];
            MMA16816(d[0][nt], a[0], bfrag);
            MMA16816(d[1][nt], a[1], bfrag);
        }
    }
    __syncthreads();

    // epilogue: two px-halves through Tbuf[128][66]
    float* Tb = reinterpret_cast<float*>(smem);
    #pragma unroll
    for (int ph = 0; ph < 2; ph++){
        if ((wid >> 2) == ph){
            #pragma unroll
            for (int mt = 0; mt < 2; mt++){
                int ch = m0 + mt*16 + g;
                #pragma unroll
                for (int nt = 0; nt < 8; nt++){
                    int px = nt*8 + 2*tg;
                    *reinterpret_cast<float2*>(&Tb[ch*66 + px])     = make_float2(d[mt][nt][0], d[mt][nt][1]);
                    *reinterpret_cast<float2*>(&Tb[(ch+8)*66 + px]) = make_float2(d[mt][nt][2], d[mt][nt][3]);
                }
            }
        }
        __syncthreads();
        int px0 = hw0 + ph*64;
        #pragma unroll
        for (int i = 0; i < 8; i++){       // y1: pixel-major, lane = ch
            int px = wid + 8*i;
            g_y1[((size_t)b*HWSZ + px0 + px)*32 + lane] = Tb[lane*66 + px];
        }
        #pragma unroll
        for (int i = 0; i < 8; i++){       // y2: channel-major, lane = px
            int idx = wid + 8*i;
            int c = idx >> 1, pg = idx & 1;
            g_y2T[((size_t)b*32 + c)*HWSZ + px0 + pg*32 + lane] = Tb[(32+c)*66 + pg*32 + lane];
        }
        #pragma unroll
        for (int i = 0; i < 16; i++){      // y3: channel-major, lane = px
            int idx = wid + 8*i;
            int c = idx >> 1, pg = idx & 1;
            g_y3[((size_t)b*64 + c)*HWSZ + px0 + pg*32 + lane] = Tb[(64+c)*66 + pg*32 + lane];
        }
        __syncthreads();
    }
}

// ---------------------------------------------------------------------------
// attn_tiled: unchanged (tile 8x32, lanes=pixels, smem-staged)
// ---------------------------------------------------------------------------
#define PITCH 341
#define HALO  340

__global__ void __launch_bounds__(256) attn_tiled(const float* __restrict__ x,
                                                  const float* __restrict__ gamma,
                                                  float* __restrict__ out){
    __shared__ float sm[32*PITCH];
    int t = threadIdx.x, lane = t & 31, wi = t >> 5;
    int b = blockIdx.z, h0 = blockIdx.y*8, w0 = blockIdx.x*32;
    size_t pb = (size_t)b << 18;

    for (int hp = wi; hp < HALO; hp += 8){
        int hr = hp / 34, hc = hp - hr*34;
        int nh = min(max(h0 + hr - 1, 0), 511);
        int nw = min(max(w0 + hc - 1, 0), 511);
        sm[lane*PITCH + hp] = g_y1[(pb + (size_t)((nh<<9) + nw))*32 + lane];
    }
    __syncthreads();

    int hbase = (wi+1)*34 + lane + 1;
    float av[9];
    {
        float acct[9];
        #pragma unroll
        for (int n = 0; n < 9; n++) acct[n] = 0.f;
        const float* x2p = g_y2T + ((size_t)b*32)*HWSZ + (size_t)(((h0+wi)<<9) + w0 + lane);
        #pragma unroll 4
        for (int c = 0; c < 32; c++){
            float x2h = 0.5f * __ldg(x2p + (size_t)c*HWSZ);
            #pragma unroll
            for (int n = 0; n < 9; n++){
                const int D = (n/3 - 1)*34 + (n%3 - 1);
                float th;
                asm("tanh.approx.f32 %0, %1;" : "=f"(th) : "f"(sm[c*PITCH + hbase + D] * x2h));
                acct[n] += th;
            }
        }
        #pragma unroll
        for (int n = 0; n < 9; n++){
            int nh = h0 + wi + n/3 - 1, nw = w0 + lane + n%3 - 1;
            bool ok = ((unsigned)nh < 512u) && ((unsigned)nw < 512u);
            av[n] = ok ? fmaf(0.5f, acct[n], 16.0f) : 0.f;
        }
    }

    float gm = __ldg(gamma);
    for (int ch0 = 0; ch0 < 64; ch0 += 16){
        __syncthreads();
        for (int cc = wi; cc < 16; cc += 8){
            const float* src = g_y3 + ((size_t)(b*64 + ch0 + cc))*HWSZ;
            for (int hp = lane; hp < HALO; hp += 32){
                int hr = hp / 34, hc = hp - hr*34;
                int nh = min(max(h0 + hr - 1, 0), 511);
                int nw = min(max(w0 + hc - 1, 0), 511);
                sm[cc*PITCH + hp] = src[(nh<<9) + nw];
            }
        }
        __syncthreads();
        size_t obase = ((size_t)(b*64 + ch0))*HWSZ + (size_t)(((h0+wi)<<9) + w0 + lane);
        #pragma unroll
        for (int j = 0; j < 16; j++){
            float acc = 0.f;
            #pragma unroll
            for (int n = 0; n < 9; n++){
                const int D = (n/3 - 1)*34 + (n%3 - 1);
                acc = fmaf(sm[j*PITCH + hbase + D], av[n], acc);
            }
            size_t o = obase + (size_t)j*HWSZ;
            out[o] = x[o] + gm * acc;
        }
    }
}

extern "C" void kernel_launch(void* const* d_in, const int* in_sizes, int n_in,
                              void* d_out, int out_size){
    const float* x     = (const float*)d_in[0];
    const float* w1    = (const float*)d_in[1];
    const float* b1    = (const float*)d_in[2];
    const float* w2    = (const float*)d_in[3];
    const float* b2    = (const float*)d_in[4];
    const float* w3    = (const float*)d_in[5];
    const float* b3    = (const float*)d_in[6];
    const float* gamma = (const float*)d_in[7];
    float* out = (float*)d_out;

    cudaFuncSetAttribute(conv_mma, cudaFuncAttributeMaxDynamicSharedMemorySize, CONV_SMEM);
    pack_weights<<<1, 256>>>(w1, b1, w2, b2, w3, b3);
    conv_mma<<<(BATCH*HWSZ)/128, 256, CONV_SMEM>>>(x);
    attn_tiled<<<dim3(16, 64, BATCH), 256>>>(x, gamma, out);
}

// round 9
// speedup vs baseline: 1.9374x; 1.4761x over previous
#include <cuda_runtime.h>
#include <cuda_fp16.h>
#include <cstdint>

#define HWSZ (512*512)
#define BATCH 4

// fp16 scratch:
// g_y1h: pixel-major half2 channel-pairs [p][16]
// g_y2h: channel-major half [b][32][hw]
// g_y3h: channel-pair planes half2 [b][32cp][hw]
__device__ __align__(16) __half2 g_y1h[(size_t)BATCH*HWSZ*16];
__device__ __align__(16) __half  g_y2h[(size_t)BATCH*32*HWSZ];
__device__ __align__(16) __half2 g_y3h[(size_t)BATCH*32*HWSZ];

__device__ __forceinline__ unsigned swz(unsigned b){ return b ^ ((b >> 3) & 0x70); }

// ---------------------------------------------------------------------------
// conv_mma: D[128 out][128 px] per CTA via mma.sync m16n8k16 (f16 in, f32 acc).
// Weights converted+swizzled per-CTA from global (no separate pack launch).
// smem: ws @0 (16KB), xs @16384 (16KB); Tbuf float[128][66] overlays. 33792 B.
// ---------------------------------------------------------------------------
#define XS_OFF 16384
#define CONV_SMEM 33792

#define MMA16816(D, A, B) \
    asm volatile("mma.sync.aligned.m16n8k16.row.col.f32.f16.f16.f32 " \
        "{%0,%1,%2,%3}, {%4,%5,%6,%7}, {%8,%9}, {%0,%1,%2,%3};" \
        : "+f"((D)[0]), "+f"((D)[1]), "+f"((D)[2]), "+f"((D)[3]) \
        : "r"((A)[0]), "r"((A)[1]), "r"((A)[2]), "r"((A)[3]), "r"((B)[0]), "r"((B)[1]))

__global__ void __launch_bounds__(256) conv_mma(const float* __restrict__ x,
        const float* __restrict__ w1, const float* __restrict__ b1,
        const float* __restrict__ w2, const float* __restrict__ b2,
        const float* __restrict__ w3, const float* __restrict__ b3){
    extern __shared__ char smem[];
    int t = threadIdx.x, lane = t & 31, wid = t >> 5;
    int g = lane >> 2, tg = lane & 3;

    int tile = blockIdx.x;
    int b = tile >> 11;
    int hw0 = (tile & 2047) << 7;
    const float* xb = x + ((size_t)b * 64) * HWSZ + hw0;

    // stage weights: convert + swizzle from global (rows: w1, w2, w3)
    {
        __half* ws = reinterpret_cast<__half*>(smem);
        #pragma unroll
        for (int i = 0; i < 32; i++){
            int idx = t + 256*i;
            int o = idx >> 6, c = idx & 63;
            float v = (o < 32) ? w1[o*64 + c] : (o < 64) ? w2[(o-32)*64 + c] : w3[(o-64)*64 + c];
            ws[swz((unsigned)o*128u + (unsigned)c*2u) >> 1] = __float2half(v);
        }
    }
    // stage x: row = px (128B = 64 ch fp16), swizzled. 2 threads per px.
    {
        int px = t >> 1, cb = (t & 1) * 32;
        #pragma unroll
        for (int cq = 0; cq < 8; cq++){
            int c = cb + cq*4;
            __half2 h0 = __floats2half2_rn(xb[(size_t)c*HWSZ + px],     xb[(size_t)(c+1)*HWSZ + px]);
            __half2 h1 = __floats2half2_rn(xb[(size_t)(c+2)*HWSZ + px], xb[(size_t)(c+3)*HWSZ + px]);
            uint2 pkt;
            pkt.x = *reinterpret_cast<uint32_t*>(&h0);
            pkt.y = *reinterpret_cast<uint32_t*>(&h1);
            *reinterpret_cast<uint2*>(smem + XS_OFF + swz((unsigned)px*128u + (unsigned)c*2u)) = pkt;
        }
    }
    __syncthreads();

    int m0 = (wid & 3) * 32, n0 = (wid >> 2) * 64;

    float d[2][8][4];
    #pragma unroll
    for (int mt = 0; mt < 2; mt++){
        int chl = m0 + mt*16 + g, chh = chl + 8;
        float blo = (chl < 32) ? b1[chl] : (chl < 64) ? b2[chl-32] : b3[chl-64];
        float bhi = (chh < 32) ? b1[chh] : (chh < 64) ? b2[chh-32] : b3[chh-64];
        #pragma unroll
        for (int nt = 0; nt < 8; nt++){
            d[mt][nt][0] = blo; d[mt][nt][1] = blo;
            d[mt][nt][2] = bhi; d[mt][nt][3] = bhi;
        }
    }

    const uint32_t* wsv = reinterpret_cast<const uint32_t*>(smem);
    const uint32_t* xsv = reinterpret_cast<const uint32_t*>(smem + XS_OFF);

    #pragma unroll
    for (int ks = 0; ks < 4; ks++){
        uint32_t a[2][4];
        #pragma unroll
        for (int mt = 0; mt < 2; mt++){
            unsigned r0 = (unsigned)(m0 + mt*16 + g);
            unsigned c0 = (unsigned)(ks*32 + tg*4);
            a[mt][0] = wsv[swz(r0*128u + c0) >> 2];
            a[mt][1] = wsv[swz((r0+8)*128u + c0) >> 2];
            a[mt][2] = wsv[swz(r0*128u + c0 + 16) >> 2];
            a[mt][3] = wsv[swz((r0+8)*128u + c0 + 16) >> 2];
        }
        #pragma unroll
        for (int nt = 0; nt < 8; nt++){
            unsigned pr = (unsigned)(n0 + nt*8 + g);
            unsigned bb = pr*128u + (unsigned)(ks*32 + tg*4);
            uint32_t bfrag[2];
            bfrag[0] = xsv[swz(bb) >> 2];
            bfrag[1] = xsv[swz(bb + 16) >> 2];
            MMA16816(d[0][nt], a[0], bfrag);
            MMA16816(d[1][nt], a[1], bfrag);
        }
    }
    __syncthreads();

    // epilogue: two px-halves through Tbuf[128][66], fp16 outputs
    float* Tb = reinterpret_cast<float*>(smem);
    #pragma unroll
    for (int ph = 0; ph < 2; ph++){
        if ((wid >> 2) == ph){
            #pragma unroll
            for (int mt = 0; mt < 2; mt++){
                int ch = m0 + mt*16 + g;
                #pragma unroll
                for (int nt = 0; nt < 8; nt++){
                    int px = nt*8 + 2*tg;
                    *reinterpret_cast<float2*>(&Tb[ch*66 + px])     = make_float2(d[mt][nt][0], d[mt][nt][1]);
                    *reinterpret_cast<float2*>(&Tb[(ch+8)*66 + px]) = make_float2(d[mt][nt][2], d[mt][nt][3]);
                }
            }
        }
        __syncthreads();
        int px0 = hw0 + ph*64;
        #pragma unroll
        for (int i = 0; i < 4; i++){       // y1h: pixel-major half2 pairs
            int e = t + 256*i;             // 0..1023
            int cp = e & 15, px = e >> 4;
            g_y1h[((size_t)b*HWSZ + px0 + px)*16 + cp] =
                __floats2half2_rn(Tb[(2*cp)*66 + px], Tb[(2*cp+1)*66 + px]);
        }
        #pragma unroll
        for (int i = 0; i < 8; i++){       // y2h: channel-major half
            int e = t + 256*i;             // 0..2047
            int c = e >> 6, px = e & 63;
            g_y2h[((size_t)b*32 + c)*HWSZ + px0 + px] = __float2half(Tb[(32+c)*66 + px]);
        }
        #pragma unroll
        for (int i = 0; i < 8; i++){       // y3h: channel-pair planes half2
            int e = t + 256*i;
            int cp = e >> 6, px = e & 63;
            g_y3h[((size_t)b*32 + cp)*HWSZ + px0 + px] =
                __floats2half2_rn(Tb[(64+2*cp)*66 + px], Tb[(64+2*cp+1)*66 + px]);
        }
        __syncthreads();
    }
}

// ---------------------------------------------------------------------------
// attn_tiled: tile 8x32, lanes=pixels. half2 channel-pairs in smem.
// sm1: x1 halo [16cp][PITCH] (uint32=half2); sm3: y3 chunk [8cp][PITCH].
// ---------------------------------------------------------------------------
#define PITCH 341
#define HALO  340

__global__ void __launch_bounds__(256) attn_tiled(const float* __restrict__ x,
                                                  const float* __restrict__ gamma,
                                                  float* __restrict__ out){
    __shared__ uint32_t sm1[16*PITCH];
    __shared__ uint32_t sm3[8*PITCH];
    int t = threadIdx.x, lane = t & 31, wi = t >> 5;
    int b = blockIdx.z, h0 = blockIdx.y*8, w0 = blockIdx.x*32;
    size_t pb = (size_t)b << 18;

    // stage x1 halo (half2 pairs, verbatim uint32 copy)
    {
        const uint32_t* y1v = reinterpret_cast<const uint32_t*>(g_y1h);
        for (int e = t; e < HALO*16; e += 256){
            int hp = e >> 4, cp = e & 15;
            int hr = hp / 34, hc = hp - hr*34;
            int nh = min(max(h0 + hr - 1, 0), 511);
            int nw = min(max(w0 + hc - 1, 0), 511);
            sm1[cp*PITCH + hp] = y1v[(pb + (size_t)((nh<<9) + nw))*16 + cp];
        }
    }
    __syncthreads();

    int hbase = (wi+1)*34 + lane + 1;
    float av[9];
    {
        float acct[9];
        #pragma unroll
        for (int n = 0; n < 9; n++) acct[n] = 0.f;
        const __half* x2p = g_y2h + ((size_t)b*32)*HWSZ + (size_t)(((h0+wi)<<9) + w0 + lane);
        #pragma unroll 4
        for (int cp = 0; cp < 16; cp++){
            float xa = 0.5f * __half2float(__ldg(x2p + (size_t)(2*cp)*HWSZ));
            float xc = 0.5f * __half2float(__ldg(x2p + (size_t)(2*cp+1)*HWSZ));
            #pragma unroll
            for (int n = 0; n < 9; n++){
                const int D = (n/3 - 1)*34 + (n%3 - 1);
                float2 f = __half22float2(*reinterpret_cast<const __half2*>(&sm1[cp*PITCH + hbase + D]));
                float t0, t1;
                asm("tanh.approx.f32 %0, %1;" : "=f"(t0) : "f"(f.x * xa));
                asm("tanh.approx.f32 %0, %1;" : "=f"(t1) : "f"(f.y * xc));
                acct[n] += t0 + t1;
            }
        }
        #pragma unroll
        for (int n = 0; n < 9; n++){
            int nh = h0 + wi + n/3 - 1, nw = w0 + lane + n%3 - 1;
            bool ok = ((unsigned)nh < 512u) && ((unsigned)nw < 512u);
            av[n] = ok ? fmaf(0.5f, acct[n], 16.0f) : 0.f;
        }
    }

    float gm = __ldg(gamma);
    int hw = ((h0+wi)<<9) + w0 + lane;
    #pragma unroll 1
    for (int ch = 0; ch < 4; ch++){
        __syncthreads();
        {   // warp wi stages channel-pair plane (ch*8 + wi)
            const uint32_t* src = reinterpret_cast<const uint32_t*>(
                g_y3h + ((size_t)(b*32 + ch*8 + wi))*HWSZ);
            for (int hp = lane; hp < HALO; hp += 32){
                int hr = hp / 34, hc = hp - hr*34;
                int nh = min(max(h0 + hr - 1, 0), 511);
                int nw = min(max(w0 + hc - 1, 0), 511);
                sm3[wi*PITCH + hp] = src[(nh<<9) + nw];
            }
        }
        __syncthreads();
        size_t obase = ((size_t)(b*64 + ch*16))*HWSZ + hw;
        #pragma unroll
        for (int cpl = 0; cpl < 8; cpl++){
            float a0 = 0.f, a1 = 0.f;
            #pragma unroll
            for (int n = 0; n < 9; n++){
                const int D = (n/3 - 1)*34 + (n%3 - 1);
                float2 f = __half22float2(*reinterpret_cast<const __half2*>(&sm3[cpl*PITCH + hbase + D]));
                a0 = fmaf(f.x, av[n], a0);
                a1 = fmaf(f.y, av[n], a1);
            }
            size_t o0 = obase + (size_t)(2*cpl)*HWSZ;
            size_t o1 = o0 + HWSZ;
            out[o0] = x[o0] + gm * a0;
            out[o1] = x[o1] + gm * a1;
        }
    }
}

extern "C" void kernel_launch(void* const* d_in, const int* in_sizes, int n_in,
                              void* d_out, int out_size){
    const float* x     = (const float*)d_in[0];
    const float* w1    = (const float*)d_in[1];
    const float* b1    = (const float*)d_in[2];
    const float* w2    = (const float*)d_in[3];
    const float* b2    = (const float*)d_in[4];
    const float* w3    = (const float*)d_in[5];
    const float* b3    = (const float*)d_in[6];
    const float* gamma = (const float*)d_in[7];
    float* out = (float*)d_out;

    cudaFuncSetAttribute(conv_mma, cudaFuncAttributeMaxDynamicSharedMemorySize, CONV_SMEM);
    conv_mma<<<(BATCH*HWSZ)/128, 256, CONV_SMEM>>>(x, w1, b1, w2, b2, w3, b3);
    attn_tiled<<<dim3(16, 64, BATCH), 256>>>(x, gamma, out);
}